// round 9
// baseline (speedup 1.0000x reference)
#include <cuda_runtime.h>
#include <math.h>

// Problem constants (fixed shapes for this problem instance)
#define Zc 512
#define Hc 256
#define NMAX 20000
#define BMAX 32
#define DPB 16     // docs per block in doc kernel (4 per thread)
#define SDOCS 8    // docs per block in score kernel
#define KMAX 8     // final output k bound
#define K1 8       // per-warp candidate depth in stage1
#define SEG 16     // stage-1 segments per query (x4 warps = 64 slices)
#define NCAND (SEG * 4 * K1)   // 512 candidates per query

// doc_kernel dynamic smem: dup-pair x tile + activation tile
#define DOC_SMEM_BYTES (DPB * Zc * 8 + DPB * Hc * 4)   // 65536 + 16384 = 81920

// Scratch (no allocations allowed anywhere)
__device__ float g_qb[BMAX * Hc];                 // qa + b1, [B,H]
__device__ float g_da[(size_t)NMAX * Hc];         // d_t @ W1[H:], [N,H]
__device__ float g_scores[(size_t)BMAX * NMAX];   // APPROX scaled scores [B,N]
__device__ unsigned long long g_part[BMAX * NCAND]; // stage-1 candidate keys

typedef unsigned long long u64;

__device__ __forceinline__ u64 pk2(float a, float b) {
    u64 r; asm("mov.b64 %0, {%1,%2};" : "=l"(r) : "f"(a), "f"(b)); return r;
}
__device__ __forceinline__ void fma2(u64 &d, u64 a, u64 b) {
    asm("fma.rn.f32x2 %0, %1, %2, %0;" : "+l"(d) : "l"(a), "l"(b));
}
__device__ __forceinline__ float2 up2(u64 v) {
    float lo, hi; asm("mov.b64 {%0,%1}, %2;" : "=f"(lo), "=f"(hi) : "l"(v));
    return make_float2(lo, hi);
}

__device__ __forceinline__ float gelu_f(float x) {
    // exact gelu: 0.5*x*(1+erf(x/sqrt(2)))
    return 0.5f * x * (1.0f + erff(x * 0.70710678118654752440f));
}

// fast approximate gelu (tanh formulation, hardware tanh.approx) — used ONLY
// for the candidate-scoring pass; winners are re-scored exactly.
__device__ __forceinline__ float gelu_a(float x) {
    float x2 = x * x;
    float inner = x * fmaf(0.035677408136f, x2, 0.7978845608028654f);
    float th;
    asm("tanh.approx.f32 %0, %1;" : "=f"(th) : "f"(inner));
    return 0.5f * x * (1.0f + th);
}

// ---------------------------------------------------------------------------
// Kernel 1: query path.  grid = B, block = 256 (one thread per h)
// ---------------------------------------------------------------------------
__global__ __launch_bounds__(256) void query_kernel(
    const float* __restrict__ q, const float* __restrict__ Wq,
    const float* __restrict__ bq, const float* __restrict__ lnw,
    const float* __restrict__ lnb, const float* __restrict__ W1,
    const float* __restrict__ b1)
{
    __shared__ float xq[Zc];
    __shared__ float qt[Hc];
    __shared__ float red[18];
    int b = blockIdx.x, t = threadIdx.x;
    const float* row = q + (size_t)b * Zc;
    for (int i = t; i < Zc; i += 256) xq[i] = row[i];
    __syncthreads();

    float acc = bq[t];
    #pragma unroll 8
    for (int z = 0; z < Zc; z++) acc = fmaf(xq[z], Wq[z * Hc + t], acc);
    float g = gelu_f(acc);

    float s = g, s2 = g * g;
    #pragma unroll
    for (int o = 16; o; o >>= 1) {
        s  += __shfl_down_sync(0xffffffffu, s, o);
        s2 += __shfl_down_sync(0xffffffffu, s2, o);
    }
    if ((t & 31) == 0) { red[t >> 5] = s; red[8 + (t >> 5)] = s2; }
    __syncthreads();
    if (t == 0) {
        float S = 0.f, S2 = 0.f;
        for (int w = 0; w < 8; w++) { S += red[w]; S2 += red[8 + w]; }
        float mu = S / (float)Hc;
        red[16] = mu;
        red[17] = S2 / (float)Hc - mu * mu;
    }
    __syncthreads();
    float mu = red[16], var = red[17];
    float v = (g - mu) * rsqrtf(var + 1e-5f) * lnw[t] + lnb[t];
    qt[t] = v;
    __syncthreads();

    float a2 = b1[t];  // fold b1 here
    #pragma unroll 8
    for (int j = 0; j < Hc; j++) a2 = fmaf(qt[j], W1[j * Hc + t], a2);
    g_qb[b * Hc + t] = a2;
}

// ---------------------------------------------------------------------------
// Kernel 2: doc path, fused. grid = N/DPB, block = 256, DYNAMIC smem 80 KB.
// GEMM1 reads x from PRE-DUPLICATED smem pairs (x,x) and weights via u64
// reinterpret of the 16B-aligned float4 row — zero pack-MOVs in the hot loop.
// FMA ordering identical to previous rounds -> g_da bitwise unchanged.
// hg = tid&63 owns h = 4*hg..4*hg+3; ds = tid>>6 owns docs {ds,ds+4,ds+8,ds+12}.
// ---------------------------------------------------------------------------
__global__ __launch_bounds__(256) void doc_kernel(
    const float* __restrict__ docs, const float* __restrict__ Wd,
    const float* __restrict__ bd, const float* __restrict__ lnw,
    const float* __restrict__ lnb, const float* __restrict__ W1, int N)
{
    extern __shared__ char dsm[];
    u64   (*xsd)[Zc] = (u64 (*)[Zc])dsm;                       // 64 KB dup pairs
    float (*dt)[Hc]  = (float (*)[Hc])(dsm + DPB * Zc * 8);    // 16 KB activations

    int t = threadIdx.x;
    int hg = t & 63, ds = t >> 6;
    int h4 = hg * 4;
    int docBase = blockIdx.x * DPB;

    // stage doc rows, duplicating each scalar into a (x,x) u64 pair:
    // one LDG.128 -> two STS.128 of (x,x,y,y) and (z,z,w,w)
    {
        const float4* src = (const float4*)(docs + (size_t)docBase * Zc);
        float4* dstp = (float4*)&xsd[0][0];
        #pragma unroll
        for (int i = t; i < DPB * Zc / 4; i += 256) {
            float4 v = src[i];
            dstp[i * 2 + 0] = make_float4(v.x, v.x, v.y, v.y);
            dstp[i * 2 + 1] = make_float4(v.z, v.z, v.w, v.w);
        }
    }
    __syncthreads();

    // GEMM1: d = x @ Wd + bd  (each thread: 4h x 4docs, packed f32x2 over h)
    float4 bd4 = *(const float4*)&bd[h4];
    u64 aA[4], aB[4];
    {
        u64 bdA = pk2(bd4.x, bd4.y), bdB = pk2(bd4.z, bd4.w);
        #pragma unroll
        for (int i = 0; i < 4; i++) { aA[i] = bdA; aB[i] = bdB; }
    }
    for (int z4 = 0; z4 < Zc / 4; z4++) {
        u64 xx[4][4];
        #pragma unroll
        for (int i = 0; i < 4; i++) {
            const u64* xr = &xsd[ds + 4 * i][z4 * 4];
            xx[i][0] = xr[0]; xx[i][1] = xr[1];
            xx[i][2] = xr[2]; xx[i][3] = xr[3];
        }
        #pragma unroll
        for (int u = 0; u < 4; u++) {
            const u64* wp64 = (const u64*)&Wd[(size_t)(z4 * 4 + u) * Hc + h4];
            u64 wA = wp64[0], wB = wp64[1];
            #pragma unroll
            for (int i = 0; i < 4; i++) {
                fma2(aA[i], wA, xx[i][u]);
                fma2(aB[i], wB, xx[i][u]);
            }
        }
    }
    #pragma unroll
    for (int i = 0; i < 4; i++) {
        float2 pA = up2(aA[i]), pB = up2(aB[i]);
        dt[ds + 4 * i][h4 + 0] = gelu_f(pA.x);
        dt[ds + 4 * i][h4 + 1] = gelu_f(pA.y);
        dt[ds + 4 * i][h4 + 2] = gelu_f(pB.x);
        dt[ds + 4 * i][h4 + 3] = gelu_f(pB.y);
    }
    __syncthreads();

    // LayerNorm per doc: warp w normalizes docs 2w, 2w+1
    {
        int wid = t >> 5, lane = t & 31;
        #pragma unroll
        for (int dd = 0; dd < 2; dd++) {
            float* r = dt[wid * 2 + dd];
            float s = 0.f, s2 = 0.f;
            #pragma unroll
            for (int j = lane; j < Hc; j += 32) { float v = r[j]; s += v; s2 += v * v; }
            #pragma unroll
            for (int o = 16; o; o >>= 1) {
                s  += __shfl_xor_sync(0xffffffffu, s, o);
                s2 += __shfl_xor_sync(0xffffffffu, s2, o);
            }
            float mu = s / (float)Hc;
            float rin = rsqrtf(s2 / (float)Hc - mu * mu + 1e-5f);
            #pragma unroll
            for (int j = lane; j < Hc; j += 32)
                r[j] = (r[j] - mu) * rin * lnw[j] + lnb[j];
        }
    }
    __syncthreads();

    // GEMM2: da = dt @ W1[H:2H]  (packed f32x2; weights via u64 reinterpret)
    u64 cA[4], cB[4];
    {
        u64 z = pk2(0.f, 0.f);
        #pragma unroll
        for (int i = 0; i < 4; i++) { cA[i] = z; cB[i] = z; }
    }
    for (int j4 = 0; j4 < Hc / 4; j4++) {
        float4 x0 = *(const float4*)&dt[ds][j4 * 4];
        float4 x1 = *(const float4*)&dt[ds + 4][j4 * 4];
        float4 x2 = *(const float4*)&dt[ds + 8][j4 * 4];
        float4 x3 = *(const float4*)&dt[ds + 12][j4 * 4];
        float xv[4][4] = {{x0.x, x0.y, x0.z, x0.w}, {x1.x, x1.y, x1.z, x1.w},
                          {x2.x, x2.y, x2.z, x2.w}, {x3.x, x3.y, x3.z, x3.w}};
        #pragma unroll
        for (int u = 0; u < 4; u++) {
            const u64* wp64 = (const u64*)&W1[(size_t)(Hc + j4 * 4 + u) * Hc + h4];
            u64 wA = wp64[0], wB = wp64[1];
            #pragma unroll
            for (int i = 0; i < 4; i++) {
                u64 xx = pk2(xv[i][u], xv[i][u]);
                fma2(cA[i], wA, xx);
                fma2(cB[i], wB, xx);
            }
        }
    }
    #pragma unroll
    for (int i = 0; i < 4; i++) {
        float2 pA = up2(cA[i]), pB = up2(cB[i]);
        ((float4*)&g_da[(size_t)(docBase + ds + 4 * i) * Hc])[hg] =
            make_float4(pA.x, pA.y, pB.x, pB.y);
    }
}

// ---------------------------------------------------------------------------
// Kernel 3: APPROXIMATE pairwise scoring.  grid = N/SDOCS, block = 256.
// gelu via hardware tanh.approx; winners re-scored exactly in rerank.
// ---------------------------------------------------------------------------
__global__ __launch_bounds__(256) void score_kernel(
    const float* __restrict__ W2, const float* __restrict__ b2,
    const float* __restrict__ temp, int N)
{
    __shared__ float qbs[BMAX * Hc];   // 32 KB
    __shared__ float das[SDOCS][Hc];   // 8 KB
    __shared__ float w2s[Hc];
    int t = threadIdx.x;

    const float4* qsrc = (const float4*)g_qb;
    float4* qdst = (float4*)qbs;
    #pragma unroll
    for (int i = t; i < BMAX * Hc / 4; i += 256) qdst[i] = qsrc[i];
    w2s[t] = W2[t];
    int docBase = blockIdx.x * SDOCS;
    {
        const float4* dsrc = (const float4*)(g_da + (size_t)docBase * Hc);
        float4* ddst = (float4*)&das[0][0];
        ddst[t] = dsrc[t];
        ddst[t + 256] = dsrc[t + 256];
    }
    __syncthreads();

    float invt = 1.0f / (fabsf(temp[0]) + 1e-8f);
    float bb = b2[0];
    int w = t >> 5, lane = t & 31;

    float wv[8];
    #pragma unroll
    for (int j = 0; j < 8; j++) wv[j] = w2s[lane + 32 * j];

    float qv[4][8];
    #pragma unroll
    for (int bi = 0; bi < 4; bi++) {
        const float* qrow = &qbs[(w + 8 * bi) * Hc];
        #pragma unroll
        for (int j = 0; j < 8; j++) qv[bi][j] = qrow[lane + 32 * j];
    }

    #pragma unroll
    for (int d = 0; d < SDOCS; d++) {
        float dv[8];
        #pragma unroll
        for (int j = 0; j < 8; j++) dv[j] = das[d][lane + 32 * j];
        float acc0 = 0.f, acc1 = 0.f, acc2 = 0.f, acc3 = 0.f;
        #pragma unroll
        for (int j = 0; j < 8; j++) {
            float wj = wv[j], dj = dv[j];
            acc0 = fmaf(gelu_a(qv[0][j] + dj), wj, acc0);
            acc1 = fmaf(gelu_a(qv[1][j] + dj), wj, acc1);
            acc2 = fmaf(gelu_a(qv[2][j] + dj), wj, acc2);
            acc3 = fmaf(gelu_a(qv[3][j] + dj), wj, acc3);
        }
        #pragma unroll
        for (int o = 16; o; o >>= 1) {
            acc0 += __shfl_down_sync(0xffffffffu, acc0, o);
            acc1 += __shfl_down_sync(0xffffffffu, acc1, o);
            acc2 += __shfl_down_sync(0xffffffffu, acc2, o);
            acc3 += __shfl_down_sync(0xffffffffu, acc3, o);
        }
        if (lane == 0) {
            g_scores[(size_t)(w +  0) * N + docBase + d] = (acc0 + bb) * invt;
            g_scores[(size_t)(w +  8) * N + docBase + d] = (acc1 + bb) * invt;
            g_scores[(size_t)(w + 16) * N + docBase + d] = (acc2 + bb) * invt;
            g_scores[(size_t)(w + 24) * N + docBase + d] = (acc3 + bb) * invt;
        }
    }
}

// ---------------------------------------------------------------------------
// Top-k keys: (score, index) packed into one orderable uint64.
// Tie-break: equal score -> smaller index (low word = ~index).
// ---------------------------------------------------------------------------
__device__ __forceinline__ unsigned long long pack_key(float s, int i) {
    unsigned int u = __float_as_uint(s);
    u = (u & 0x80000000u) ? ~u : (u | 0x80000000u);
    return ((unsigned long long)u << 32) | (unsigned int)(~(unsigned int)i);
}

// ---------------------------------------------------------------------------
// Kernel 4a: per-warp top-8 candidates (approx scores). grid=(SEG,B), b=128.
// Pure shuffle argmax, no block barriers.  64 slices x 8 = 512 cands/query.
// ---------------------------------------------------------------------------
__global__ __launch_bounds__(128) void topk_stage1(int N)
{
    int seg = blockIdx.x, b = blockIdx.y, t = threadIdx.x;
    int nseg = gridDim.x;
    int seglen = (N + nseg - 1) / nseg;
    int start = seg * seglen;
    int end = start + seglen; if (end > N) end = N;

    unsigned long long loc[K1];
    #pragma unroll
    for (int j = 0; j < K1; j++) loc[j] = 0ull;

    const float* row = g_scores + (size_t)b * N;
    for (int i = start + t; i < end; i += 128) {
        unsigned long long key = pack_key(row[i], i);
        if (key > loc[K1 - 1]) {
            #pragma unroll
            for (int j = 0; j < K1; j++) {
                unsigned long long cur = loc[j];
                bool gt = key > cur;
                loc[j] = gt ? key : cur;
                key    = gt ? cur : key;
            }
        }
    }

    int wid = t >> 5, lane = t & 31;
    unsigned long long* outp = &g_part[b * NCAND + ((seg * 4 + wid) * K1)];
    #pragma unroll
    for (int r = 0; r < K1; r++) {
        unsigned long long m = loc[0];
        #pragma unroll
        for (int o = 16; o; o >>= 1) {
            unsigned long long v = __shfl_xor_sync(0xffffffffu, m, o);
            m = (v > m) ? v : m;
        }
        if (lane == 0) outp[r] = m;
        if (loc[0] == m) {
            #pragma unroll
            for (int j = 0; j < K1 - 1; j++) loc[j] = loc[j + 1];
            loc[K1 - 1] = 0ull;
        }
    }
}

// ---------------------------------------------------------------------------
// Kernel 4b: EXACT rerank of 512 candidates + top-k + softmax.  grid = B.
// Identical per-lane accumulation + shuffle order as the exact score kernel,
// so winning scores are bitwise reproduced.
// ---------------------------------------------------------------------------
__global__ __launch_bounds__(256) void rerank_kernel(
    const int* __restrict__ kptr, const float* __restrict__ W2,
    const float* __restrict__ b2, const float* __restrict__ temp,
    float* __restrict__ out, int N, int B)
{
    __shared__ float qbs[Hc];
    __shared__ float w2s[Hc];
    __shared__ unsigned long long skeys[NCAND];   // 4 KB
    __shared__ unsigned long long warpmax[8];
    __shared__ unsigned long long bestsh;

    int b = blockIdx.x, t = threadIdx.x;
    int k = *kptr; if (k > KMAX) k = KMAX; if (k < 1) k = 1;

    qbs[t] = g_qb[b * Hc + t];
    w2s[t] = W2[t];
    __syncthreads();

    float invt = 1.0f / (fabsf(temp[0]) + 1e-8f);
    float bb = b2[0];
    int w = t >> 5, lane = t & 31;

    float wv[8], qv[8];
    #pragma unroll
    for (int j = 0; j < 8; j++) {
        wv[j] = w2s[lane + 32 * j];
        qv[j] = qbs[lane + 32 * j];
    }

    // warp w handles candidates [w*64, w*64+64)
    const unsigned long long* cands = &g_part[b * NCAND];
    for (int i = 0; i < NCAND / 8; i++) {
        int c = w * (NCAND / 8) + i;
        unsigned long long key = cands[c];
        int idx = (int)(~(unsigned int)(key & 0xffffffffu));
        if (idx < 0) idx = 0; if (idx >= N) idx = N - 1;
        const float* drow = g_da + (size_t)idx * Hc;
        float acc = 0.f;
        #pragma unroll
        for (int j = 0; j < 8; j++) {
            float x = qv[j] + drow[lane + 32 * j];
            acc = fmaf(gelu_f(x), wv[j], acc);
        }
        #pragma unroll
        for (int o = 16; o; o >>= 1)
            acc += __shfl_down_sync(0xffffffffu, acc, o);
        if (lane == 0)
            skeys[c] = pack_key((acc + bb) * invt, idx);
    }
    __syncthreads();

    // top-k over 512 exact keys: thread t owns skeys[t], skeys[t+256]
    unsigned long long m0 = skeys[t], m1 = skeys[t + 256];
    unsigned long long keys[KMAX];
    for (int r = 0; r < k; r++) {
        unsigned long long m = (m0 > m1) ? m0 : m1;
        #pragma unroll
        for (int o = 16; o; o >>= 1) {
            unsigned long long v = __shfl_xor_sync(0xffffffffu, m, o);
            m = (v > m) ? v : m;
        }
        if (lane == 0) warpmax[w] = m;
        __syncthreads();
        if (t == 0) {
            unsigned long long best = 0ull;
            #pragma unroll
            for (int ww = 0; ww < 8; ww++)
                best = (warpmax[ww] > best) ? warpmax[ww] : best;
            bestsh = best;
        }
        __syncthreads();
        unsigned long long best = bestsh;
        if (t == 0) keys[r] = best;
        if (m0 == best) m0 = 0ull;
        if (m1 == best) m1 = 0ull;
        __syncthreads();
    }

    if (t == 0) {
        float gv[KMAX]; int gi[KMAX];
        for (int r = 0; r < k; r++) {
            unsigned int hi = (unsigned int)(keys[r] >> 32);
            unsigned int u = (hi & 0x80000000u) ? (hi ^ 0x80000000u) : ~hi;
            gv[r] = __uint_as_float(u);
            gi[r] = (int)(~(unsigned int)(keys[r] & 0xffffffffu));
        }
        float mx = gv[0], sum = 0.f, ex[KMAX];
        for (int j = 0; j < k; j++) { ex[j] = expf(gv[j] - mx); sum += ex[j]; }
        float inv = 1.0f / sum;
        for (int j = 0; j < k; j++) {
            out[b * k + j] = (float)gi[j];            // top_idx (as float)
            out[B * k + b * k + j] = ex[j] * inv;     // probs
        }
    }
}

// ---------------------------------------------------------------------------
extern "C" void kernel_launch(void* const* d_in, const int* in_sizes, int n_in,
                              void* d_out, int out_size)
{
    const float* query = (const float*)d_in[0];
    const float* docs  = (const float*)d_in[1];
    const int*   kptr  = (const int*)d_in[2];
    const float* Wq    = (const float*)d_in[3];
    const float* bq    = (const float*)d_in[4];
    const float* lnqw  = (const float*)d_in[5];
    const float* lnqb  = (const float*)d_in[6];
    const float* Wd    = (const float*)d_in[7];
    const float* bd    = (const float*)d_in[8];
    const float* lndw  = (const float*)d_in[9];
    const float* lndb  = (const float*)d_in[10];
    const float* W1    = (const float*)d_in[11];
    const float* b1    = (const float*)d_in[12];
    const float* W2    = (const float*)d_in[13];
    const float* b2    = (const float*)d_in[14];
    const float* temp  = (const float*)d_in[15];

    int H = in_sizes[4];            // 256
    int Z = in_sizes[3] / H;        // 512
    int B = in_sizes[0] / Z;        // 32
    int N = in_sizes[1] / Z;        // 20000

    // opt-in to >48KB dynamic smem for doc_kernel (attribute setter: not a
    // stream op / alloc / sync — legal during graph capture; idempotent)
    cudaFuncSetAttribute(doc_kernel,
                         cudaFuncAttributeMaxDynamicSharedMemorySize,
                         DOC_SMEM_BYTES);

    query_kernel<<<B, 256>>>(query, Wq, bq, lnqw, lnqb, W1, b1);
    doc_kernel<<<(N + DPB - 1) / DPB, 256, DOC_SMEM_BYTES>>>(
        docs, Wd, bd, lndw, lndb, W1, N);
    score_kernel<<<N / SDOCS, 256>>>(W2, b2, temp, N);
    dim3 g1(SEG, B);
    topk_stage1<<<g1, 128>>>(N);
    rerank_kernel<<<B, 256>>>(kptr, W2, b2, temp, (float*)d_out, N, B);
}

// round 10
// speedup vs baseline: 1.1107x; 1.1107x over previous
#include <cuda_runtime.h>
#include <math.h>

// Problem constants (fixed shapes for this problem instance)
#define Zc 512
#define Hc 256
#define NMAX 20000
#define BMAX 32
#define DPB 32     // docs per block in doc kernel (4 per thread, 512 threads)
#define SDOCS 8    // docs per block in score kernel
#define KMAX 8     // final output k bound
#define K1 8       // per-warp candidate depth in stage1
#define SEG 16     // stage-1 segments per query (x4 warps = 64 slices)
#define NCAND (SEG * 4 * K1)   // 512 candidates per query

// doc_kernel dynamic smem: raw x tile + activation tile
#define DOC_SMEM_BYTES (DPB * Zc * 4 + DPB * Hc * 4)   // 65536 + 32768 = 98304

// Scratch (no allocations allowed anywhere)
__device__ float g_qb[BMAX * Hc];                 // qa + b1, [B,H]
__device__ float g_da[(size_t)NMAX * Hc];         // d_t @ W1[H:], [N,H]
__device__ float g_scores[(size_t)BMAX * NMAX];   // APPROX scaled scores [B,N]
__device__ unsigned long long g_part[BMAX * NCAND]; // stage-1 candidate keys

typedef unsigned long long u64;

__device__ __forceinline__ u64 pk2(float a, float b) {
    u64 r; asm("mov.b64 %0, {%1,%2};" : "=l"(r) : "f"(a), "f"(b)); return r;
}
__device__ __forceinline__ void fma2(u64 &d, u64 a, u64 b) {
    asm("fma.rn.f32x2 %0, %1, %2, %0;" : "+l"(d) : "l"(a), "l"(b));
}
__device__ __forceinline__ float2 up2(u64 v) {
    float lo, hi; asm("mov.b64 {%0,%1}, %2;" : "=f"(lo), "=f"(hi) : "l"(v));
    return make_float2(lo, hi);
}

__device__ __forceinline__ float gelu_f(float x) {
    // exact gelu: 0.5*x*(1+erf(x/sqrt(2)))
    return 0.5f * x * (1.0f + erff(x * 0.70710678118654752440f));
}

// fast approximate gelu (tanh formulation, hardware tanh.approx) — used ONLY
// for the candidate-scoring pass; winners are re-scored exactly.
__device__ __forceinline__ float gelu_a(float x) {
    float x2 = x * x;
    float inner = x * fmaf(0.035677408136f, x2, 0.7978845608028654f);
    float th;
    asm("tanh.approx.f32 %0, %1;" : "=f"(th) : "f"(inner));
    return 0.5f * x * (1.0f + th);
}

// ---------------------------------------------------------------------------
// Kernel 1: query path.  grid = B, block = 256 (one thread per h)
// ---------------------------------------------------------------------------
__global__ __launch_bounds__(256) void query_kernel(
    const float* __restrict__ q, const float* __restrict__ Wq,
    const float* __restrict__ bq, const float* __restrict__ lnw,
    const float* __restrict__ lnb, const float* __restrict__ W1,
    const float* __restrict__ b1)
{
    __shared__ float xq[Zc];
    __shared__ float qt[Hc];
    __shared__ float red[18];
    int b = blockIdx.x, t = threadIdx.x;
    const float* row = q + (size_t)b * Zc;
    for (int i = t; i < Zc; i += 256) xq[i] = row[i];
    __syncthreads();

    float acc = bq[t];
    #pragma unroll 8
    for (int z = 0; z < Zc; z++) acc = fmaf(xq[z], Wq[z * Hc + t], acc);
    float g = gelu_f(acc);

    float s = g, s2 = g * g;
    #pragma unroll
    for (int o = 16; o; o >>= 1) {
        s  += __shfl_down_sync(0xffffffffu, s, o);
        s2 += __shfl_down_sync(0xffffffffu, s2, o);
    }
    if ((t & 31) == 0) { red[t >> 5] = s; red[8 + (t >> 5)] = s2; }
    __syncthreads();
    if (t == 0) {
        float S = 0.f, S2 = 0.f;
        for (int w = 0; w < 8; w++) { S += red[w]; S2 += red[8 + w]; }
        float mu = S / (float)Hc;
        red[16] = mu;
        red[17] = S2 / (float)Hc - mu * mu;
    }
    __syncthreads();
    float mu = red[16], var = red[17];
    float v = (g - mu) * rsqrtf(var + 1e-5f) * lnw[t] + lnb[t];
    qt[t] = v;
    __syncthreads();

    float a2 = b1[t];  // fold b1 here
    #pragma unroll 8
    for (int j = 0; j < Hc; j++) a2 = fmaf(qt[j], W1[j * Hc + t], a2);
    g_qb[b * Hc + t] = a2;
}

// ---------------------------------------------------------------------------
// Kernel 2: doc path, fused. grid = N/DPB, block = 512, dynamic smem 96 KB.
// Per-thread math IDENTICAL to the proven R7 kernel (4 docs x 4h, packed
// f32x2, same FMA order -> g_da bitwise unchanged); only the block geometry
// scales: 32 docs/block halves Wd/W1 L2 traffic vs 16 docs/block.
// hg = tid&63 owns h = 4*hg..4*hg+3; ds = tid>>6 in [0,8) owns docs
// {ds, ds+8, ds+16, ds+24}.
// ---------------------------------------------------------------------------
__global__ __launch_bounds__(512) void doc_kernel(
    const float* __restrict__ docs, const float* __restrict__ Wd,
    const float* __restrict__ bd, const float* __restrict__ lnw,
    const float* __restrict__ lnb, const float* __restrict__ W1, int N)
{
    extern __shared__ char dsm[];
    float (*xs)[Zc] = (float (*)[Zc])dsm;                      // 64 KB raw rows
    float (*dt)[Hc] = (float (*)[Hc])(dsm + DPB * Zc * 4);     // 32 KB activations

    int t = threadIdx.x;
    int hg = t & 63, ds = t >> 6;      // ds in [0,8)
    int h4 = hg * 4;
    int docBase = blockIdx.x * DPB;

    {
        const float4* src = (const float4*)(docs + (size_t)docBase * Zc);
        float4* dstp = (float4*)&xs[0][0];
        #pragma unroll
        for (int i = t; i < DPB * Zc / 4; i += 512) dstp[i] = src[i];
    }
    __syncthreads();

    // GEMM1: d = x @ Wd + bd  (each thread: 4h x 4docs, packed f32x2 over h)
    float4 bd4 = *(const float4*)&bd[h4];
    u64 aA[4], aB[4];
    {
        u64 bdA = pk2(bd4.x, bd4.y), bdB = pk2(bd4.z, bd4.w);
        #pragma unroll
        for (int i = 0; i < 4; i++) { aA[i] = bdA; aB[i] = bdB; }
    }
    for (int z4 = 0; z4 < Zc / 4; z4++) {
        float4 x0 = *(const float4*)&xs[ds][z4 * 4];
        float4 x1 = *(const float4*)&xs[ds + 8][z4 * 4];
        float4 x2 = *(const float4*)&xs[ds + 16][z4 * 4];
        float4 x3 = *(const float4*)&xs[ds + 24][z4 * 4];
        float xv[4][4] = {{x0.x, x0.y, x0.z, x0.w}, {x1.x, x1.y, x1.z, x1.w},
                          {x2.x, x2.y, x2.z, x2.w}, {x3.x, x3.y, x3.z, x3.w}};
        #pragma unroll
        for (int u = 0; u < 4; u++) {
            const u64* wp64 = (const u64*)&Wd[(size_t)(z4 * 4 + u) * Hc + h4];
            u64 wA = wp64[0], wB = wp64[1];
            #pragma unroll
            for (int i = 0; i < 4; i++) {
                u64 xx = pk2(xv[i][u], xv[i][u]);
                fma2(aA[i], wA, xx);
                fma2(aB[i], wB, xx);
            }
        }
    }
    #pragma unroll
    for (int i = 0; i < 4; i++) {
        float2 pA = up2(aA[i]), pB = up2(aB[i]);
        dt[ds + 8 * i][h4 + 0] = gelu_f(pA.x);
        dt[ds + 8 * i][h4 + 1] = gelu_f(pA.y);
        dt[ds + 8 * i][h4 + 2] = gelu_f(pB.x);
        dt[ds + 8 * i][h4 + 3] = gelu_f(pB.y);
    }
    __syncthreads();

    // LayerNorm per doc: warp w (of 16) normalizes docs 2w, 2w+1
    {
        int wid = t >> 5, lane = t & 31;
        #pragma unroll
        for (int dd = 0; dd < 2; dd++) {
            float* r = dt[wid * 2 + dd];
            float s = 0.f, s2 = 0.f;
            #pragma unroll
            for (int j = lane; j < Hc; j += 32) { float v = r[j]; s += v; s2 += v * v; }
            #pragma unroll
            for (int o = 16; o; o >>= 1) {
                s  += __shfl_xor_sync(0xffffffffu, s, o);
                s2 += __shfl_xor_sync(0xffffffffu, s2, o);
            }
            float mu = s / (float)Hc;
            float rin = rsqrtf(s2 / (float)Hc - mu * mu + 1e-5f);
            #pragma unroll
            for (int j = lane; j < Hc; j += 32)
                r[j] = (r[j] - mu) * rin * lnw[j] + lnb[j];
        }
    }
    __syncthreads();

    // GEMM2: da = dt @ W1[H:2H]  (packed f32x2; weights via u64 reinterpret)
    u64 cA[4], cB[4];
    {
        u64 z = pk2(0.f, 0.f);
        #pragma unroll
        for (int i = 0; i < 4; i++) { cA[i] = z; cB[i] = z; }
    }
    for (int j4 = 0; j4 < Hc / 4; j4++) {
        float4 x0 = *(const float4*)&dt[ds][j4 * 4];
        float4 x1 = *(const float4*)&dt[ds + 8][j4 * 4];
        float4 x2 = *(const float4*)&dt[ds + 16][j4 * 4];
        float4 x3 = *(const float4*)&dt[ds + 24][j4 * 4];
        float xv[4][4] = {{x0.x, x0.y, x0.z, x0.w}, {x1.x, x1.y, x1.z, x1.w},
                          {x2.x, x2.y, x2.z, x2.w}, {x3.x, x3.y, x3.z, x3.w}};
        #pragma unroll
        for (int u = 0; u < 4; u++) {
            const u64* wp64 = (const u64*)&W1[(size_t)(Hc + j4 * 4 + u) * Hc + h4];
            u64 wA = wp64[0], wB = wp64[1];
            #pragma unroll
            for (int i = 0; i < 4; i++) {
                u64 xx = pk2(xv[i][u], xv[i][u]);
                fma2(cA[i], wA, xx);
                fma2(cB[i], wB, xx);
            }
        }
    }
    #pragma unroll
    for (int i = 0; i < 4; i++) {
        float2 pA = up2(cA[i]), pB = up2(cB[i]);
        ((float4*)&g_da[(size_t)(docBase + ds + 8 * i) * Hc])[hg] =
            make_float4(pA.x, pA.y, pB.x, pB.y);
    }
}

// ---------------------------------------------------------------------------
// Kernel 3: APPROXIMATE pairwise scoring.  grid = N/SDOCS, block = 256.
// gelu via hardware tanh.approx; winners re-scored exactly in rerank.
// ---------------------------------------------------------------------------
__global__ __launch_bounds__(256) void score_kernel(
    const float* __restrict__ W2, const float* __restrict__ b2,
    const float* __restrict__ temp, int N)
{
    __shared__ float qbs[BMAX * Hc];   // 32 KB
    __shared__ float das[SDOCS][Hc];   // 8 KB
    __shared__ float w2s[Hc];
    int t = threadIdx.x;

    const float4* qsrc = (const float4*)g_qb;
    float4* qdst = (float4*)qbs;
    #pragma unroll
    for (int i = t; i < BMAX * Hc / 4; i += 256) qdst[i] = qsrc[i];
    w2s[t] = W2[t];
    int docBase = blockIdx.x * SDOCS;
    {
        const float4* dsrc = (const float4*)(g_da + (size_t)docBase * Hc);
        float4* ddst = (float4*)&das[0][0];
        ddst[t] = dsrc[t];
        ddst[t + 256] = dsrc[t + 256];
    }
    __syncthreads();

    float invt = 1.0f / (fabsf(temp[0]) + 1e-8f);
    float bb = b2[0];
    int w = t >> 5, lane = t & 31;

    float wv[8];
    #pragma unroll
    for (int j = 0; j < 8; j++) wv[j] = w2s[lane + 32 * j];

    float qv[4][8];
    #pragma unroll
    for (int bi = 0; bi < 4; bi++) {
        const float* qrow = &qbs[(w + 8 * bi) * Hc];
        #pragma unroll
        for (int j = 0; j < 8; j++) qv[bi][j] = qrow[lane + 32 * j];
    }

    #pragma unroll
    for (int d = 0; d < SDOCS; d++) {
        float dv[8];
        #pragma unroll
        for (int j = 0; j < 8; j++) dv[j] = das[d][lane + 32 * j];
        float acc0 = 0.f, acc1 = 0.f, acc2 = 0.f, acc3 = 0.f;
        #pragma unroll
        for (int j = 0; j < 8; j++) {
            float wj = wv[j], dj = dv[j];
            acc0 = fmaf(gelu_a(qv[0][j] + dj), wj, acc0);
            acc1 = fmaf(gelu_a(qv[1][j] + dj), wj, acc1);
            acc2 = fmaf(gelu_a(qv[2][j] + dj), wj, acc2);
            acc3 = fmaf(gelu_a(qv[3][j] + dj), wj, acc3);
        }
        #pragma unroll
        for (int o = 16; o; o >>= 1) {
            acc0 += __shfl_down_sync(0xffffffffu, acc0, o);
            acc1 += __shfl_down_sync(0xffffffffu, acc1, o);
            acc2 += __shfl_down_sync(0xffffffffu, acc2, o);
            acc3 += __shfl_down_sync(0xffffffffu, acc3, o);
        }
        if (lane == 0) {
            g_scores[(size_t)(w +  0) * N + docBase + d] = (acc0 + bb) * invt;
            g_scores[(size_t)(w +  8) * N + docBase + d] = (acc1 + bb) * invt;
            g_scores[(size_t)(w + 16) * N + docBase + d] = (acc2 + bb) * invt;
            g_scores[(size_t)(w + 24) * N + docBase + d] = (acc3 + bb) * invt;
        }
    }
}

// ---------------------------------------------------------------------------
// Top-k keys: (score, index) packed into one orderable uint64.
// Tie-break: equal score -> smaller index (low word = ~index).
// ---------------------------------------------------------------------------
__device__ __forceinline__ unsigned long long pack_key(float s, int i) {
    unsigned int u = __float_as_uint(s);
    u = (u & 0x80000000u) ? ~u : (u | 0x80000000u);
    return ((unsigned long long)u << 32) | (unsigned int)(~(unsigned int)i);
}

// ---------------------------------------------------------------------------
// Kernel 4a: per-warp top-8 candidates (approx scores). grid=(SEG,B), b=128.
// Pure shuffle argmax, no block barriers.  64 slices x 8 = 512 cands/query.
// ---------------------------------------------------------------------------
__global__ __launch_bounds__(128) void topk_stage1(int N)
{
    int seg = blockIdx.x, b = blockIdx.y, t = threadIdx.x;
    int nseg = gridDim.x;
    int seglen = (N + nseg - 1) / nseg;
    int start = seg * seglen;
    int end = start + seglen; if (end > N) end = N;

    unsigned long long loc[K1];
    #pragma unroll
    for (int j = 0; j < K1; j++) loc[j] = 0ull;

    const float* row = g_scores + (size_t)b * N;
    for (int i = start + t; i < end; i += 128) {
        unsigned long long key = pack_key(row[i], i);
        if (key > loc[K1 - 1]) {
            #pragma unroll
            for (int j = 0; j < K1; j++) {
                unsigned long long cur = loc[j];
                bool gt = key > cur;
                loc[j] = gt ? key : cur;
                key    = gt ? cur : key;
            }
        }
    }

    int wid = t >> 5, lane = t & 31;
    unsigned long long* outp = &g_part[b * NCAND + ((seg * 4 + wid) * K1)];
    #pragma unroll
    for (int r = 0; r < K1; r++) {
        unsigned long long m = loc[0];
        #pragma unroll
        for (int o = 16; o; o >>= 1) {
            unsigned long long v = __shfl_xor_sync(0xffffffffu, m, o);
            m = (v > m) ? v : m;
        }
        if (lane == 0) outp[r] = m;
        if (loc[0] == m) {
            #pragma unroll
            for (int j = 0; j < K1 - 1; j++) loc[j] = loc[j + 1];
            loc[K1 - 1] = 0ull;
        }
    }
}

// ---------------------------------------------------------------------------
// Kernel 4b: EXACT rerank of 512 candidates + top-k + softmax.  grid = B.
// Identical per-lane accumulation + shuffle order as the exact score kernel,
// so winning scores are bitwise reproduced.
// ---------------------------------------------------------------------------
__global__ __launch_bounds__(256) void rerank_kernel(
    const int* __restrict__ kptr, const float* __restrict__ W2,
    const float* __restrict__ b2, const float* __restrict__ temp,
    float* __restrict__ out, int N, int B)
{
    __shared__ float qbs[Hc];
    __shared__ float w2s[Hc];
    __shared__ unsigned long long skeys[NCAND];   // 4 KB
    __shared__ unsigned long long warpmax[8];
    __shared__ unsigned long long bestsh;

    int b = blockIdx.x, t = threadIdx.x;
    int k = *kptr; if (k > KMAX) k = KMAX; if (k < 1) k = 1;

    qbs[t] = g_qb[b * Hc + t];
    w2s[t] = W2[t];
    __syncthreads();

    float invt = 1.0f / (fabsf(temp[0]) + 1e-8f);
    float bb = b2[0];
    int w = t >> 5, lane = t & 31;

    float wv[8], qv[8];
    #pragma unroll
    for (int j = 0; j < 8; j++) {
        wv[j] = w2s[lane + 32 * j];
        qv[j] = qbs[lane + 32 * j];
    }

    // warp w handles candidates [w*64, w*64+64)
    const unsigned long long* cands = &g_part[b * NCAND];
    for (int i = 0; i < NCAND / 8; i++) {
        int c = w * (NCAND / 8) + i;
        unsigned long long key = cands[c];
        int idx = (int)(~(unsigned int)(key & 0xffffffffu));
        if (idx < 0) idx = 0; if (idx >= N) idx = N - 1;
        const float* drow = g_da + (size_t)idx * Hc;
        float acc = 0.f;
        #pragma unroll
        for (int j = 0; j < 8; j++) {
            float x = qv[j] + drow[lane + 32 * j];
            acc = fmaf(gelu_f(x), wv[j], acc);
        }
        #pragma unroll
        for (int o = 16; o; o >>= 1)
            acc += __shfl_down_sync(0xffffffffu, acc, o);
        if (lane == 0)
            skeys[c] = pack_key((acc + bb) * invt, idx);
    }
    __syncthreads();

    // top-k over 512 exact keys: thread t owns skeys[t], skeys[t+256]
    unsigned long long m0 = skeys[t], m1 = skeys[t + 256];
    unsigned long long keys[KMAX];
    for (int r = 0; r < k; r++) {
        unsigned long long m = (m0 > m1) ? m0 : m1;
        #pragma unroll
        for (int o = 16; o; o >>= 1) {
            unsigned long long v = __shfl_xor_sync(0xffffffffu, m, o);
            m = (v > m) ? v : m;
        }
        if (lane == 0) warpmax[w] = m;
        __syncthreads();
        if (t == 0) {
            unsigned long long best = 0ull;
            #pragma unroll
            for (int ww = 0; ww < 8; ww++)
                best = (warpmax[ww] > best) ? warpmax[ww] : best;
            bestsh = best;
        }
        __syncthreads();
        unsigned long long best = bestsh;
        if (t == 0) keys[r] = best;
        if (m0 == best) m0 = 0ull;
        if (m1 == best) m1 = 0ull;
        __syncthreads();
    }

    if (t == 0) {
        float gv[KMAX]; int gi[KMAX];
        for (int r = 0; r < k; r++) {
            unsigned int hi = (unsigned int)(keys[r] >> 32);
            unsigned int u = (hi & 0x80000000u) ? (hi ^ 0x80000000u) : ~hi;
            gv[r] = __uint_as_float(u);
            gi[r] = (int)(~(unsigned int)(keys[r] & 0xffffffffu));
        }
        float mx = gv[0], sum = 0.f, ex[KMAX];
        for (int j = 0; j < k; j++) { ex[j] = expf(gv[j] - mx); sum += ex[j]; }
        float inv = 1.0f / sum;
        for (int j = 0; j < k; j++) {
            out[b * k + j] = (float)gi[j];            // top_idx (as float)
            out[B * k + b * k + j] = ex[j] * inv;     // probs
        }
    }
}

// ---------------------------------------------------------------------------
extern "C" void kernel_launch(void* const* d_in, const int* in_sizes, int n_in,
                              void* d_out, int out_size)
{
    const float* query = (const float*)d_in[0];
    const float* docs  = (const float*)d_in[1];
    const int*   kptr  = (const int*)d_in[2];
    const float* Wq    = (const float*)d_in[3];
    const float* bq    = (const float*)d_in[4];
    const float* lnqw  = (const float*)d_in[5];
    const float* lnqb  = (const float*)d_in[6];
    const float* Wd    = (const float*)d_in[7];
    const float* bd    = (const float*)d_in[8];
    const float* lndw  = (const float*)d_in[9];
    const float* lndb  = (const float*)d_in[10];
    const float* W1    = (const float*)d_in[11];
    const float* b1    = (const float*)d_in[12];
    const float* W2    = (const float*)d_in[13];
    const float* b2    = (const float*)d_in[14];
    const float* temp  = (const float*)d_in[15];

    int H = in_sizes[4];            // 256
    int Z = in_sizes[3] / H;        // 512
    int B = in_sizes[0] / Z;        // 32
    int N = in_sizes[1] / Z;        // 20000

    // opt-in to >48KB dynamic smem for doc_kernel (attribute setter: not a
    // stream op / alloc / sync — legal during graph capture; idempotent)
    cudaFuncSetAttribute(doc_kernel,
                         cudaFuncAttributeMaxDynamicSharedMemorySize,
                         DOC_SMEM_BYTES);

    query_kernel<<<B, 256>>>(query, Wq, bq, lnqw, lnqb, W1, b1);
    doc_kernel<<<(N + DPB - 1) / DPB, 512, DOC_SMEM_BYTES>>>(
        docs, Wd, bd, lndw, lndb, W1, N);
    score_kernel<<<N / SDOCS, 256>>>(W2, b2, temp, N);
    dim3 g1(SEG, B);
    topk_stage1<<<g1, 128>>>(N);
    rerank_kernel<<<B, 256>>>(kptr, W2, b2, temp, (float*)d_out, N, B);
}

// round 11
// speedup vs baseline: 1.2074x; 1.0871x over previous
#include <cuda_runtime.h>
#include <math.h>

// Problem constants (fixed shapes for this problem instance)
#define Zc 512
#define Hc 256
#define NMAX 20000
#define BMAX 32
#define DPB 16     // docs per block in doc kernel (4 per thread) — R7 optimum
#define SDOCS 8    // docs per block in score kernel
#define KMAX 8     // final output k bound
#define K1 8       // per-warp candidate depth in stage1
#define SEG 16     // stage-1 segments per query (x4 warps = 64 slices)
#define NCAND (SEG * 4 * K1)   // 512 candidates per query

// Scratch (no allocations allowed anywhere)
__device__ float g_qb[BMAX * Hc];                 // qa + b1, [B,H]
__device__ float g_da[(size_t)NMAX * Hc];         // d_t @ W1[H:], [N,H]
__device__ float g_scores[(size_t)BMAX * NMAX];   // APPROX scaled scores [B,N]
__device__ unsigned long long g_part[BMAX * NCAND]; // stage-1 candidate keys

typedef unsigned long long u64;

__device__ __forceinline__ u64 pk2(float a, float b) {
    u64 r; asm("mov.b64 %0, {%1,%2};" : "=l"(r) : "f"(a), "f"(b)); return r;
}
__device__ __forceinline__ void fma2(u64 &d, u64 a, u64 b) {
    asm("fma.rn.f32x2 %0, %1, %2, %0;" : "+l"(d) : "l"(a), "l"(b));
}
__device__ __forceinline__ u64 fma2g(u64 a, u64 b, u64 c) {
    u64 d; asm("fma.rn.f32x2 %0, %1, %2, %3;" : "=l"(d) : "l"(a), "l"(b), "l"(c));
    return d;
}
__device__ __forceinline__ u64 add2(u64 a, u64 b) {
    u64 d; asm("add.rn.f32x2 %0, %1, %2;" : "=l"(d) : "l"(a), "l"(b)); return d;
}
__device__ __forceinline__ u64 mul2(u64 a, u64 b) {
    u64 d; asm("mul.rn.f32x2 %0, %1, %2;" : "=l"(d) : "l"(a), "l"(b)); return d;
}
__device__ __forceinline__ float2 up2(u64 v) {
    float lo, hi; asm("mov.b64 {%0,%1}, %2;" : "=f"(lo), "=f"(hi) : "l"(v));
    return make_float2(lo, hi);
}
__device__ __forceinline__ float tanh_ap(float x) {
    float th; asm("tanh.approx.f32 %0, %1;" : "=f"(th) : "f"(x)); return th;
}

__device__ __forceinline__ float gelu_f(float x) {
    // exact gelu: 0.5*x*(1+erf(x/sqrt(2)))
    return 0.5f * x * (1.0f + erff(x * 0.70710678118654752440f));
}

// ---------------------------------------------------------------------------
// Kernel 1: query path.  grid = B, block = 256 (one thread per h)
// ---------------------------------------------------------------------------
__global__ __launch_bounds__(256) void query_kernel(
    const float* __restrict__ q, const float* __restrict__ Wq,
    const float* __restrict__ bq, const float* __restrict__ lnw,
    const float* __restrict__ lnb, const float* __restrict__ W1,
    const float* __restrict__ b1)
{
    __shared__ float xq[Zc];
    __shared__ float qt[Hc];
    __shared__ float red[18];
    int b = blockIdx.x, t = threadIdx.x;
    const float* row = q + (size_t)b * Zc;
    for (int i = t; i < Zc; i += 256) xq[i] = row[i];
    __syncthreads();

    float acc = bq[t];
    #pragma unroll 8
    for (int z = 0; z < Zc; z++) acc = fmaf(xq[z], Wq[z * Hc + t], acc);
    float g = gelu_f(acc);

    float s = g, s2 = g * g;
    #pragma unroll
    for (int o = 16; o; o >>= 1) {
        s  += __shfl_down_sync(0xffffffffu, s, o);
        s2 += __shfl_down_sync(0xffffffffu, s2, o);
    }
    if ((t & 31) == 0) { red[t >> 5] = s; red[8 + (t >> 5)] = s2; }
    __syncthreads();
    if (t == 0) {
        float S = 0.f, S2 = 0.f;
        for (int w = 0; w < 8; w++) { S += red[w]; S2 += red[8 + w]; }
        float mu = S / (float)Hc;
        red[16] = mu;
        red[17] = S2 / (float)Hc - mu * mu;
    }
    __syncthreads();
    float mu = red[16], var = red[17];
    float v = (g - mu) * rsqrtf(var + 1e-5f) * lnw[t] + lnb[t];
    qt[t] = v;
    __syncthreads();

    float a2 = b1[t];  // fold b1 here
    #pragma unroll 8
    for (int j = 0; j < Hc; j++) a2 = fmaf(qt[j], W1[j * Hc + t], a2);
    g_qb[b * Hc + t] = a2;
}

// ---------------------------------------------------------------------------
// Kernel 2: doc path, fused — EXACT R7 configuration (proven 395.9us run).
// grid = N/DPB, block = 256, 48 KB static smem.
// hg = tid&63 owns h = 4*hg..4*hg+3; ds = tid>>6 owns docs {ds,ds+4,ds+8,ds+12}.
// ---------------------------------------------------------------------------
__global__ __launch_bounds__(256) void doc_kernel(
    const float* __restrict__ docs, const float* __restrict__ Wd,
    const float* __restrict__ bd, const float* __restrict__ lnw,
    const float* __restrict__ lnb, const float* __restrict__ W1, int N)
{
    __shared__ float xs[DPB][Zc];   // 32 KB: raw doc rows
    __shared__ float dt[DPB][Hc];   // 16 KB: activations
    int t = threadIdx.x;
    int hg = t & 63, ds = t >> 6;
    int h4 = hg * 4;
    int docBase = blockIdx.x * DPB;

    const float4* src = (const float4*)(docs + (size_t)docBase * Zc);
    float4* dstp = (float4*)&xs[0][0];
    #pragma unroll
    for (int i = t; i < DPB * Zc / 4; i += 256) dstp[i] = src[i];
    __syncthreads();

    // GEMM1: d = x @ Wd + bd  (each thread: 4h x 4docs, packed f32x2 over h)
    float4 bd4 = *(const float4*)&bd[h4];
    u64 aA[4], aB[4];
    {
        u64 bdA = pk2(bd4.x, bd4.y), bdB = pk2(bd4.z, bd4.w);
        #pragma unroll
        for (int i = 0; i < 4; i++) { aA[i] = bdA; aB[i] = bdB; }
    }
    for (int z4 = 0; z4 < Zc / 4; z4++) {
        float4 x0 = *(const float4*)&xs[ds][z4 * 4];
        float4 x1 = *(const float4*)&xs[ds + 4][z4 * 4];
        float4 x2 = *(const float4*)&xs[ds + 8][z4 * 4];
        float4 x3 = *(const float4*)&xs[ds + 12][z4 * 4];
        float xv[4][4] = {{x0.x, x0.y, x0.z, x0.w}, {x1.x, x1.y, x1.z, x1.w},
                          {x2.x, x2.y, x2.z, x2.w}, {x3.x, x3.y, x3.z, x3.w}};
        #pragma unroll
        for (int u = 0; u < 4; u++) {
            const u64* wp64 = (const u64*)&Wd[(size_t)(z4 * 4 + u) * Hc + h4];
            u64 wA = wp64[0], wB = wp64[1];
            #pragma unroll
            for (int i = 0; i < 4; i++) {
                u64 xx = pk2(xv[i][u], xv[i][u]);
                fma2(aA[i], wA, xx);
                fma2(aB[i], wB, xx);
            }
        }
    }
    #pragma unroll
    for (int i = 0; i < 4; i++) {
        float2 pA = up2(aA[i]), pB = up2(aB[i]);
        dt[ds + 4 * i][h4 + 0] = gelu_f(pA.x);
        dt[ds + 4 * i][h4 + 1] = gelu_f(pA.y);
        dt[ds + 4 * i][h4 + 2] = gelu_f(pB.x);
        dt[ds + 4 * i][h4 + 3] = gelu_f(pB.y);
    }
    __syncthreads();

    // LayerNorm per doc: warp w normalizes docs 2w, 2w+1
    {
        int wid = t >> 5, lane = t & 31;
        #pragma unroll
        for (int dd = 0; dd < 2; dd++) {
            float* r = dt[wid * 2 + dd];
            float s = 0.f, s2 = 0.f;
            #pragma unroll
            for (int j = lane; j < Hc; j += 32) { float v = r[j]; s += v; s2 += v * v; }
            #pragma unroll
            for (int o = 16; o; o >>= 1) {
                s  += __shfl_xor_sync(0xffffffffu, s, o);
                s2 += __shfl_xor_sync(0xffffffffu, s2, o);
            }
            float mu = s / (float)Hc;
            float rin = rsqrtf(s2 / (float)Hc - mu * mu + 1e-5f);
            #pragma unroll
            for (int j = lane; j < Hc; j += 32)
                r[j] = (r[j] - mu) * rin * lnw[j] + lnb[j];
        }
    }
    __syncthreads();

    // GEMM2: da = dt @ W1[H:2H]  (packed f32x2; weights via u64 reinterpret)
    u64 cA[4], cB[4];
    {
        u64 z = pk2(0.f, 0.f);
        #pragma unroll
        for (int i = 0; i < 4; i++) { cA[i] = z; cB[i] = z; }
    }
    for (int j4 = 0; j4 < Hc / 4; j4++) {
        float4 x0 = *(const float4*)&dt[ds][j4 * 4];
        float4 x1 = *(const float4*)&dt[ds + 4][j4 * 4];
        float4 x2 = *(const float4*)&dt[ds + 8][j4 * 4];
        float4 x3 = *(const float4*)&dt[ds + 12][j4 * 4];
        float xv[4][4] = {{x0.x, x0.y, x0.z, x0.w}, {x1.x, x1.y, x1.z, x1.w},
                          {x2.x, x2.y, x2.z, x2.w}, {x3.x, x3.y, x3.z, x3.w}};
        #pragma unroll
        for (int u = 0; u < 4; u++) {
            const u64* wp64 = (const u64*)&W1[(size_t)(Hc + j4 * 4 + u) * Hc + h4];
            u64 wA = wp64[0], wB = wp64[1];
            #pragma unroll
            for (int i = 0; i < 4; i++) {
                u64 xx = pk2(xv[i][u], xv[i][u]);
                fma2(cA[i], wA, xx);
                fma2(cB[i], wB, xx);
            }
        }
    }
    #pragma unroll
    for (int i = 0; i < 4; i++) {
        float2 pA = up2(cA[i]), pB = up2(cB[i]);
        ((float4*)&g_da[(size_t)(docBase + ds + 4 * i) * Hc])[hg] =
            make_float4(pA.x, pA.y, pB.x, pB.y);
    }
}

// ---------------------------------------------------------------------------
// Kernel 3: APPROXIMATE pairwise scoring, PACKED f32x2.  grid=N/SDOCS, b=256.
// The 4 accumulator chains pack into 2 f32x2 pairs; tanh stays scalar MUFU.
// Per-lane math identical to the scalar approx version (f32x2 is per-lane
// IEEE); winners re-scored exactly in rerank -> rel_err unchanged.
// ---------------------------------------------------------------------------
__global__ __launch_bounds__(256) void score_kernel(
    const float* __restrict__ W2, const float* __restrict__ b2,
    const float* __restrict__ temp, int N)
{
    __shared__ float qbs[BMAX * Hc];   // 32 KB
    __shared__ float das[SDOCS][Hc];   // 8 KB
    __shared__ float w2s[Hc];
    int t = threadIdx.x;

    const float4* qsrc = (const float4*)g_qb;
    float4* qdst = (float4*)qbs;
    #pragma unroll
    for (int i = t; i < BMAX * Hc / 4; i += 256) qdst[i] = qsrc[i];
    w2s[t] = W2[t];
    int docBase = blockIdx.x * SDOCS;
    {
        const float4* dsrc = (const float4*)(g_da + (size_t)docBase * Hc);
        float4* ddst = (float4*)&das[0][0];
        ddst[t] = dsrc[t];
        ddst[t + 256] = dsrc[t + 256];
    }
    __syncthreads();

    float invt = 1.0f / (fabsf(temp[0]) + 1e-8f);
    float bb = b2[0];
    int w = t >> 5, lane = t & 31;

    const u64 one2 = pk2(1.0f, 1.0f);
    const u64 cA2  = pk2(0.035677408136f, 0.035677408136f);
    const u64 cB2  = pk2(0.7978845608028654f, 0.7978845608028654f);

    // half-weights packed (0.5 folded out of gelu into the weight)
    u64 hw2[8];
    #pragma unroll
    for (int j = 0; j < 8; j++) {
        float hwj = 0.5f * w2s[lane + 32 * j];
        hw2[j] = pk2(hwj, hwj);
    }

    // packed q pairs: (b=w, b=w+8) and (b=w+16, b=w+24)
    u64 qp01[8], qp23[8];
    #pragma unroll
    for (int j = 0; j < 8; j++) {
        int h = lane + 32 * j;
        qp01[j] = pk2(qbs[(w +  0) * Hc + h], qbs[(w +  8) * Hc + h]);
        qp23[j] = pk2(qbs[(w + 16) * Hc + h], qbs[(w + 24) * Hc + h]);
    }

    #pragma unroll
    for (int d = 0; d < SDOCS; d++) {
        u64 acc01 = pk2(0.f, 0.f), acc23 = acc01;
        #pragma unroll
        for (int j = 0; j < 8; j++) {
            float dj = das[d][lane + 32 * j];
            u64 dj2 = pk2(dj, dj);
            u64 x01 = add2(qp01[j], dj2);
            u64 x23 = add2(qp23[j], dj2);
            u64 s01 = mul2(x01, x01);
            u64 s23 = mul2(x23, x23);
            u64 p01 = fma2g(cA2, s01, cB2);
            u64 p23 = fma2g(cA2, s23, cB2);
            u64 in01 = mul2(x01, p01);
            u64 in23 = mul2(x23, p23);
            float2 i01 = up2(in01), i23 = up2(in23);
            u64 th01 = pk2(tanh_ap(i01.x), tanh_ap(i01.y));
            u64 th23 = pk2(tanh_ap(i23.x), tanh_ap(i23.y));
            u64 o01 = add2(th01, one2);
            u64 o23 = add2(th23, one2);
            u64 g01 = mul2(x01, o01);       // x*(1+th); the 0.5 lives in hw2
            u64 g23 = mul2(x23, o23);
            acc01 = fma2g(g01, hw2[j], acc01);
            acc23 = fma2g(g23, hw2[j], acc23);
        }
        float2 a01 = up2(acc01), a23 = up2(acc23);
        float acc0 = a01.x, acc1 = a01.y, acc2 = a23.x, acc3 = a23.y;
        #pragma unroll
        for (int o = 16; o; o >>= 1) {
            acc0 += __shfl_down_sync(0xffffffffu, acc0, o);
            acc1 += __shfl_down_sync(0xffffffffu, acc1, o);
            acc2 += __shfl_down_sync(0xffffffffu, acc2, o);
            acc3 += __shfl_down_sync(0xffffffffu, acc3, o);
        }
        if (lane == 0) {
            g_scores[(size_t)(w +  0) * N + docBase + d] = (acc0 + bb) * invt;
            g_scores[(size_t)(w +  8) * N + docBase + d] = (acc1 + bb) * invt;
            g_scores[(size_t)(w + 16) * N + docBase + d] = (acc2 + bb) * invt;
            g_scores[(size_t)(w + 24) * N + docBase + d] = (acc3 + bb) * invt;
        }
    }
}

// ---------------------------------------------------------------------------
// Top-k keys: (score, index) packed into one orderable uint64.
// Tie-break: equal score -> smaller index (low word = ~index).
// ---------------------------------------------------------------------------
__device__ __forceinline__ unsigned long long pack_key(float s, int i) {
    unsigned int u = __float_as_uint(s);
    u = (u & 0x80000000u) ? ~u : (u | 0x80000000u);
    return ((unsigned long long)u << 32) | (unsigned int)(~(unsigned int)i);
}

// ---------------------------------------------------------------------------
// Kernel 4a: per-warp top-8 candidates (approx scores). grid=(SEG,B), b=128.
// Pure shuffle argmax, no block barriers.  64 slices x 8 = 512 cands/query.
// ---------------------------------------------------------------------------
__global__ __launch_bounds__(128) void topk_stage1(int N)
{
    int seg = blockIdx.x, b = blockIdx.y, t = threadIdx.x;
    int nseg = gridDim.x;
    int seglen = (N + nseg - 1) / nseg;
    int start = seg * seglen;
    int end = start + seglen; if (end > N) end = N;

    unsigned long long loc[K1];
    #pragma unroll
    for (int j = 0; j < K1; j++) loc[j] = 0ull;

    const float* row = g_scores + (size_t)b * N;
    for (int i = start + t; i < end; i += 128) {
        unsigned long long key = pack_key(row[i], i);
        if (key > loc[K1 - 1]) {
            #pragma unroll
            for (int j = 0; j < K1; j++) {
                unsigned long long cur = loc[j];
                bool gt = key > cur;
                loc[j] = gt ? key : cur;
                key    = gt ? cur : key;
            }
        }
    }

    int wid = t >> 5, lane = t & 31;
    unsigned long long* outp = &g_part[b * NCAND + ((seg * 4 + wid) * K1)];
    #pragma unroll
    for (int r = 0; r < K1; r++) {
        unsigned long long m = loc[0];
        #pragma unroll
        for (int o = 16; o; o >>= 1) {
            unsigned long long v = __shfl_xor_sync(0xffffffffu, m, o);
            m = (v > m) ? v : m;
        }
        if (lane == 0) outp[r] = m;
        if (loc[0] == m) {
            #pragma unroll
            for (int j = 0; j < K1 - 1; j++) loc[j] = loc[j + 1];
            loc[K1 - 1] = 0ull;
        }
    }
}

// ---------------------------------------------------------------------------
// Kernel 4b: EXACT rerank of 512 candidates + top-k + softmax.  grid = B.
// Identical per-lane accumulation + shuffle order as the exact score kernel,
// so winning scores are bitwise reproduced.
// ---------------------------------------------------------------------------
__global__ __launch_bounds__(256) void rerank_kernel(
    const int* __restrict__ kptr, const float* __restrict__ W2,
    const float* __restrict__ b2, const float* __restrict__ temp,
    float* __restrict__ out, int N, int B)
{
    __shared__ float qbs[Hc];
    __shared__ float w2s[Hc];
    __shared__ unsigned long long skeys[NCAND];   // 4 KB
    __shared__ unsigned long long warpmax[8];
    __shared__ unsigned long long bestsh;

    int b = blockIdx.x, t = threadIdx.x;
    int k = *kptr; if (k > KMAX) k = KMAX; if (k < 1) k = 1;

    qbs[t] = g_qb[b * Hc + t];
    w2s[t] = W2[t];
    __syncthreads();

    float invt = 1.0f / (fabsf(temp[0]) + 1e-8f);
    float bb = b2[0];
    int w = t >> 5, lane = t & 31;

    float wv[8], qv[8];
    #pragma unroll
    for (int j = 0; j < 8; j++) {
        wv[j] = w2s[lane + 32 * j];
        qv[j] = qbs[lane + 32 * j];
    }

    // warp w handles candidates [w*64, w*64+64)
    const unsigned long long* cands = &g_part[b * NCAND];
    for (int i = 0; i < NCAND / 8; i++) {
        int c = w * (NCAND / 8) + i;
        unsigned long long key = cands[c];
        int idx = (int)(~(unsigned int)(key & 0xffffffffu));
        if (idx < 0) idx = 0; if (idx >= N) idx = N - 1;
        const float* drow = g_da + (size_t)idx * Hc;
        float acc = 0.f;
        #pragma unroll
        for (int j = 0; j < 8; j++) {
            float x = qv[j] + drow[lane + 32 * j];
            acc = fmaf(gelu_f(x), wv[j], acc);
        }
        #pragma unroll
        for (int o = 16; o; o >>= 1)
            acc += __shfl_down_sync(0xffffffffu, acc, o);
        if (lane == 0)
            skeys[c] = pack_key((acc + bb) * invt, idx);
    }
    __syncthreads();

    // top-k over 512 exact keys: thread t owns skeys[t], skeys[t+256]
    unsigned long long m0 = skeys[t], m1 = skeys[t + 256];
    unsigned long long keys[KMAX];
    for (int r = 0; r < k; r++) {
        unsigned long long m = (m0 > m1) ? m0 : m1;
        #pragma unroll
        for (int o = 16; o; o >>= 1) {
            unsigned long long v = __shfl_xor_sync(0xffffffffu, m, o);
            m = (v > m) ? v : m;
        }
        if (lane == 0) warpmax[w] = m;
        __syncthreads();
        if (t == 0) {
            unsigned long long best = 0ull;
            #pragma unroll
            for (int ww = 0; ww < 8; ww++)
                best = (warpmax[ww] > best) ? warpmax[ww] : best;
            bestsh = best;
        }
        __syncthreads();
        unsigned long long best = bestsh;
        if (t == 0) keys[r] = best;
        if (m0 == best) m0 = 0ull;
        if (m1 == best) m1 = 0ull;
        __syncthreads();
    }

    if (t == 0) {
        float gv[KMAX]; int gi[KMAX];
        for (int r = 0; r < k; r++) {
            unsigned int hi = (unsigned int)(keys[r] >> 32);
            unsigned int u = (hi & 0x80000000u) ? (hi ^ 0x80000000u) : ~hi;
            gv[r] = __uint_as_float(u);
            gi[r] = (int)(~(unsigned int)(keys[r] & 0xffffffffu));
        }
        float mx = gv[0], sum = 0.f, ex[KMAX];
        for (int j = 0; j < k; j++) { ex[j] = expf(gv[j] - mx); sum += ex[j]; }
        float inv = 1.0f / sum;
        for (int j = 0; j < k; j++) {
            out[b * k + j] = (float)gi[j];            // top_idx (as float)
            out[B * k + b * k + j] = ex[j] * inv;     // probs
        }
    }
}

// ---------------------------------------------------------------------------
extern "C" void kernel_launch(void* const* d_in, const int* in_sizes, int n_in,
                              void* d_out, int out_size)
{
    const float* query = (const float*)d_in[0];
    const float* docs  = (const float*)d_in[1];
    const int*   kptr  = (const int*)d_in[2];
    const float* Wq    = (const float*)d_in[3];
    const float* bq    = (const float*)d_in[4];
    const float* lnqw  = (const float*)d_in[5];
    const float* lnqb  = (const float*)d_in[6];
    const float* Wd    = (const float*)d_in[7];
    const float* bd    = (const float*)d_in[8];
    const float* lndw  = (const float*)d_in[9];
    const float* lndb  = (const float*)d_in[10];
    const float* W1    = (const float*)d_in[11];
    const float* b1    = (const float*)d_in[12];
    const float* W2    = (const float*)d_in[13];
    const float* b2    = (const float*)d_in[14];
    const float* temp  = (const float*)d_in[15];

    int H = in_sizes[4];            // 256
    int Z = in_sizes[3] / H;        // 512
    int B = in_sizes[0] / Z;        // 32
    int N = in_sizes[1] / Z;        // 20000

    query_kernel<<<B, 256>>>(query, Wq, bq, lnqw, lnqb, W1, b1);
    doc_kernel<<<(N + DPB - 1) / DPB, 256>>>(docs, Wd, bd, lndw, lndb, W1, N);
    score_kernel<<<N / SDOCS, 256>>>(W2, b2, temp, N);
    dim3 g1(SEG, B);
    topk_stage1<<<g1, 128>>>(N);
    rerank_kernel<<<B, 256>>>(kptr, W2, b2, temp, (float*)d_out, N, B);
}